// round 2
// baseline (speedup 1.0000x reference)
#include <cuda_runtime.h>
#include <cuda_bf16.h>

// Problem constants
#define B_   8
#define C_   64
#define H_   128
#define W_   128
#define CO_  18      // offset channels
#define G_   8       // groups
#define CG_  8       // channels per group (in & out)
#define KK_  9
#define HW_  (H_*W_)

// Scratch: offset field stored [B, H, W, 18] (pixel-contiguous)
__device__ float g_off[B_ * H_ * W_ * CO_];

// ---------------------------------------------------------------------------
// Kernel 1: offset = prelu(conv3x3(x, ow) + ob)
// 16x16 pixel tile per block, 256 threads, 8-channel input chunks via smem.
// ---------------------------------------------------------------------------
#define TILE 16
__global__ __launch_bounds__(256) void offset_conv_kernel(
    const float* __restrict__ x,     // [B,64,H,W]
    const float* __restrict__ ow,    // [18,64,3,3]
    const float* __restrict__ ob,    // [18]
    const float* __restrict__ pa)    // [1]
{
    __shared__ float sx[8][TILE + 2][TILE + 2];   // 8 ch x 18 x 18
    __shared__ float sw[CO_][8][KK_];             // 18 x 8 x 9

    const int b  = blockIdx.z;
    const int h0 = blockIdx.y * TILE;
    const int w0 = blockIdx.x * TILE;
    const int ty = threadIdx.x / TILE;
    const int tx = threadIdx.x % TILE;

    float acc[CO_];
#pragma unroll
    for (int co = 0; co < CO_; co++) acc[co] = ob[co];

    for (int cc = 0; cc < C_ / 8; cc++) {
        __syncthreads();
        // load 8-channel halo tile (18x18 per channel), zero-padded
        for (int i = threadIdx.x; i < 8 * 18 * 18; i += 256) {
            int ci = i / (18 * 18);
            int r  = (i / 18) % 18;
            int c  = i % 18;
            int gh = h0 - 1 + r;
            int gw = w0 - 1 + c;
            float v = 0.f;
            if (gh >= 0 && gh < H_ && gw >= 0 && gw < W_)
                v = x[(((size_t)b * C_ + cc * 8 + ci) * H_ + gh) * W_ + gw];
            sx[ci][r][c] = v;
        }
        // load weight chunk
        for (int i = threadIdx.x; i < CO_ * 8 * KK_; i += 256) {
            int co = i / (8 * KK_);
            int ci = (i / KK_) % 8;
            int k  = i % KK_;
            sw[co][ci][k] = ow[((co * C_ + cc * 8 + ci) * KK_) + k];
        }
        __syncthreads();

#pragma unroll
        for (int ci = 0; ci < 8; ci++) {
#pragma unroll
            for (int k = 0; k < KK_; k++) {
                float v = sx[ci][ty + k / 3][tx + k % 3];
#pragma unroll
                for (int co = 0; co < CO_; co++)
                    acc[co] += v * sw[co][ci][k];
            }
        }
    }

    const float a = pa[0];
    float* o = g_off + (((size_t)b * H_ + (h0 + ty)) * W_ + (w0 + tx)) * CO_;
#pragma unroll
    for (int co = 0; co < CO_; co++) {
        float v = acc[co];
        o[co] = v > 0.f ? v : a * v;
    }
}

// ---------------------------------------------------------------------------
// Kernel 2: deformable conv. One thread per output pixel (all 64 out chans).
// Corner indices/weights computed once; 8 groups processed sequentially.
// Weights staged in smem transposed to [g][ci][k][co] so the co-inner loop
// reads contiguous floats (LDS.128-friendly broadcast).
// ---------------------------------------------------------------------------
__global__ void dconv_kernel(
    const float* __restrict__ x,    // [B,64,H,W]
    const float* __restrict__ dw,   // [64,8,3,3] = [g][co][ci][k]
    const float* __restrict__ db,   // [64]
    float* __restrict__ out)        // [B,64,H,W]
{
    __shared__ float sw[G_ * CG_ * KK_ * CG_];  // [g][ci][k][co], 4608 floats
    __shared__ float sb[C_];

    // transpose load: dw index = ((g*CG+co)*CG + ci)*KK + k
    for (int i = threadIdx.x; i < G_ * CG_ * CG_ * KK_; i += blockDim.x) {
        int co = i % CG_;
        int k  = (i / CG_) % KK_;
        int ci = (i / (CG_ * KK_)) % CG_;
        int g  = i / (CG_ * KK_ * CG_);
        sw[i] = dw[((g * CG_ + co) * CG_ + ci) * KK_ + k];
    }
    for (int i = threadIdx.x; i < C_; i += blockDim.x) sb[i] = db[i];
    __syncthreads();

    const int pix = blockIdx.x * blockDim.x + threadIdx.x;  // [0, B*H*W)
    const int b  = pix / HW_;
    const int hw = pix % HW_;
    const int h  = hw / W_;
    const int w  = hw % W_;

    const float* op = g_off + (size_t)pix * CO_;

    int   idx[KK_][4];
    float cw[KK_][4];
#pragma unroll
    for (int k = 0; k < KK_; k++) {
        float dy = op[2 * k];
        float dx = op[2 * k + 1];
        float py = (float)(h + (k / 3) - 1) + dy;
        float px = (float)(w + (k % 3) - 1) + dx;
        float y0f = floorf(py);
        float x0f = floorf(px);
        int   y0  = (int)y0f;
        int   x0  = (int)x0f;
        float ly = py - y0f, lx = px - x0f;
        float hy = 1.f - ly, hx = 1.f - lx;

        int y1 = y0 + 1, x1 = x0 + 1;
        bool vy0 = (y0 >= 0) & (y0 < H_);
        bool vy1 = (y1 >= 0) & (y1 < H_);
        bool vx0 = (x0 >= 0) & (x0 < W_);
        bool vx1 = (x1 >= 0) & (x1 < W_);

        int cy0 = min(max(y0, 0), H_ - 1);
        int cy1 = min(max(y1, 0), H_ - 1);
        int cx0 = min(max(x0, 0), W_ - 1);
        int cx1 = min(max(x1, 0), W_ - 1);

        idx[k][0] = cy0 * W_ + cx0;  cw[k][0] = (vy0 & vx0) ? hy * hx : 0.f;
        idx[k][1] = cy0 * W_ + cx1;  cw[k][1] = (vy0 & vx1) ? hy * lx : 0.f;
        idx[k][2] = cy1 * W_ + cx0;  cw[k][2] = (vy1 & vx0) ? ly * hx : 0.f;
        idx[k][3] = cy1 * W_ + cx1;  cw[k][3] = (vy1 & vx1) ? ly * lx : 0.f;
    }

    for (int g = 0; g < G_; g++) {
        float acc[CG_];
#pragma unroll
        for (int co = 0; co < CG_; co++) acc[co] = sb[g * CG_ + co];

        const float* wg = sw + g * CG_ * KK_ * CG_;  // [ci][k][co]

#pragma unroll
        for (int ci = 0; ci < CG_; ci++) {
            const float* base = x + ((size_t)b * C_ + g * CG_ + ci) * HW_;
#pragma unroll
            for (int k = 0; k < KK_; k++) {
                float v = cw[k][0] * __ldg(base + idx[k][0])
                        + cw[k][1] * __ldg(base + idx[k][1])
                        + cw[k][2] * __ldg(base + idx[k][2])
                        + cw[k][3] * __ldg(base + idx[k][3]);
                const float4* wv = (const float4*)(wg + (ci * KK_ + k) * CG_);
                float4 w0 = wv[0];
                float4 w1 = wv[1];
                acc[0] += v * w0.x;  acc[1] += v * w0.y;
                acc[2] += v * w0.z;  acc[3] += v * w0.w;
                acc[4] += v * w1.x;  acc[5] += v * w1.y;
                acc[6] += v * w1.z;  acc[7] += v * w1.w;
            }
        }

#pragma unroll
        for (int co = 0; co < CG_; co++)
            out[((size_t)b * C_ + g * CG_ + co) * HW_ + hw] = acc[co];
    }
}

// ---------------------------------------------------------------------------
// Launch
// ---------------------------------------------------------------------------
extern "C" void kernel_launch(void* const* d_in, const int* in_sizes, int n_in,
                              void* d_out, int out_size)
{
    const float* x    = (const float*)d_in[0];  // [8,64,128,128]
    const float* ow   = (const float*)d_in[1];  // [18,64,3,3]
    const float* ob   = (const float*)d_in[2];  // [18]
    const float* pa   = (const float*)d_in[3];  // [1]
    const float* dwgt = (const float*)d_in[4];  // [64,8,3,3]
    const float* dbia = (const float*)d_in[5];  // [64]
    float* out = (float*)d_out;

    dim3 g1(W_ / TILE, H_ / TILE, B_);          // (8, 8, 8)
    offset_conv_kernel<<<g1, 256>>>(x, ow, ob, pa);

    const int threads = 128;
    const int blocks  = (B_ * HW_) / threads;   // 1024
    dconv_kernel<<<blocks, threads>>>(x, dwgt, dbia, out);
}

// round 3
// speedup vs baseline: 1.1072x; 1.1072x over previous
#include <cuda_runtime.h>
#include <cuda_bf16.h>

// Problem constants
#define B_   8
#define C_   64
#define H_   128
#define W_   128
#define CO_  18      // offset channels
#define G_   8       // groups
#define CG_  8       // channels per group (in & out)
#define KK_  9
#define HW_  (H_*W_)

// Scratch: offset field stored [B, H, W, 18] (pixel-contiguous)
__device__ float g_off[B_ * H_ * W_ * CO_];

// ---------------------------------------------------------------------------
// Kernel 1: offset = prelu(conv3x3(x, ow) + ob)
// 16x16 pixel tile per block, 256 threads, 8-channel input chunks via smem.
// Weights staged transposed [ci][k][co(pad 20)] so the co-loop is 4x float4
// + 1x float2 vector LDS (broadcast) instead of 18 scalar LDS.
// ---------------------------------------------------------------------------
#define TILE 16
#define COP_ 20   // padded co stride (18 -> 20, keeps 16B alignment: 20*4=80B)
__global__ __launch_bounds__(256) void offset_conv_kernel(
    const float* __restrict__ x,     // [B,64,H,W]
    const float* __restrict__ ow,    // [18,64,3,3]
    const float* __restrict__ ob,    // [18]
    const float* __restrict__ pa)    // [1]
{
    __shared__ float sx[8][TILE + 2][TILE + 2];   // 8 ch x 18 x 18
    __shared__ float sw[8 * KK_ * COP_];          // [ci][k][co_pad]

    const int b  = blockIdx.z;
    const int h0 = blockIdx.y * TILE;
    const int w0 = blockIdx.x * TILE;
    const int ty = threadIdx.x / TILE;
    const int tx = threadIdx.x % TILE;

    float acc[CO_];
#pragma unroll
    for (int co = 0; co < CO_; co++) acc[co] = ob[co];

    for (int cc = 0; cc < C_ / 8; cc++) {
        __syncthreads();
        // load 8-channel halo tile (18x18 per channel), zero-padded
        for (int i = threadIdx.x; i < 8 * 18 * 18; i += 256) {
            int ci = i / (18 * 18);
            int r  = (i / 18) % 18;
            int c  = i % 18;
            int gh = h0 - 1 + r;
            int gw = w0 - 1 + c;
            float v = 0.f;
            if (gh >= 0 && gh < H_ && gw >= 0 && gw < W_)
                v = x[(((size_t)b * C_ + cc * 8 + ci) * H_ + gh) * W_ + gw];
            sx[ci][r][c] = v;
        }
        // load weight chunk, transposed to [ci][k][co]
        for (int i = threadIdx.x; i < CO_ * 8 * KK_; i += 256) {
            int co = i / (8 * KK_);
            int ci = (i / KK_) % 8;
            int k  = i % KK_;
            sw[(ci * KK_ + k) * COP_ + co] = ow[((co * C_ + cc * 8 + ci) * KK_) + k];
        }
        __syncthreads();

#pragma unroll
        for (int ci = 0; ci < 8; ci++) {
#pragma unroll
            for (int k = 0; k < KK_; k++) {
                float v = sx[ci][ty + k / 3][tx + k % 3];
                const float* wp = sw + (ci * KK_ + k) * COP_;
                float4 a0 = *(const float4*)(wp);
                float4 a1 = *(const float4*)(wp + 4);
                float4 a2 = *(const float4*)(wp + 8);
                float4 a3 = *(const float4*)(wp + 12);
                float2 a4 = *(const float2*)(wp + 16);
                acc[0]  += v * a0.x;  acc[1]  += v * a0.y;
                acc[2]  += v * a0.z;  acc[3]  += v * a0.w;
                acc[4]  += v * a1.x;  acc[5]  += v * a1.y;
                acc[6]  += v * a1.z;  acc[7]  += v * a1.w;
                acc[8]  += v * a2.x;  acc[9]  += v * a2.y;
                acc[10] += v * a2.z;  acc[11] += v * a2.w;
                acc[12] += v * a3.x;  acc[13] += v * a3.y;
                acc[14] += v * a3.z;  acc[15] += v * a3.w;
                acc[16] += v * a4.x;  acc[17] += v * a4.y;
            }
        }
    }

    const float a = pa[0];
    float* o = g_off + (((size_t)b * H_ + (h0 + ty)) * W_ + (w0 + tx)) * CO_;
#pragma unroll
    for (int co = 0; co < CO_; co++) {
        float v = acc[co];
        o[co] = v > 0.f ? v : a * v;
    }
}

// ---------------------------------------------------------------------------
// Kernel 2: deformable conv. Block = 32 pixels x 8 groups (256 threads).
// Phase A: (pixel, tap) units cooperatively compute 4 corner indices/weights
//          per tap into smem (validity folded into the weight).
// Phase B: thread (pxl, g) accumulates 8 output channels of its group:
//          9 taps x 8 input channels, 4 gathers per (tap, ci).
// ---------------------------------------------------------------------------
__global__ __launch_bounds__(256) void dconv_kernel(
    const float* __restrict__ x,    // [B,64,H,W]
    const float* __restrict__ dw,   // [64,8,3,3] = [g][co][ci][k]
    const float* __restrict__ db,   // [64]
    float* __restrict__ out)        // [B,64,H,W]
{
    __shared__ float sw[G_ * CG_ * KK_ * CG_];  // [g][ci][k][co], 4608 floats
    __shared__ float sb[C_];
    __shared__ int   s_idx[KK_][4][32];
    __shared__ float s_cw[KK_][4][32];

    // transpose-load weights: dw index = ((g*CG+co)*CG + ci)*KK + k
    for (int i = threadIdx.x; i < G_ * CG_ * CG_ * KK_; i += 256) {
        int co = i % CG_;
        int k  = (i / CG_) % KK_;
        int ci = (i / (CG_ * KK_)) % CG_;
        int g  = i / (CG_ * KK_ * CG_);
        sw[i] = dw[((g * CG_ + co) * CG_ + ci) * KK_ + k];
    }
    if (threadIdx.x < C_) sb[threadIdx.x] = db[threadIdx.x];

    const int pix0 = blockIdx.x * 32;

    // ---- Phase A: corner indices + validity-folded bilinear weights ----
    for (int u = threadIdx.x; u < 32 * KK_; u += 256) {
        const int pxl = u & 31;
        const int k   = u >> 5;
        const int pix = pix0 + pxl;
        const int hw  = pix % HW_;
        const int h   = hw / W_;
        const int w   = hw % W_;

        const float* op = g_off + (size_t)pix * CO_ + 2 * k;
        float dy = op[0];
        float dx = op[1];
        float py = (float)(h + (k / 3) - 1) + dy;
        float px = (float)(w + (k % 3) - 1) + dx;
        float y0f = floorf(py);
        float x0f = floorf(px);
        int   y0  = (int)y0f;
        int   x0  = (int)x0f;
        float ly = py - y0f, lx = px - x0f;
        float hy = 1.f - ly, hx = 1.f - lx;

        int y1 = y0 + 1, x1 = x0 + 1;
        bool vy0 = (y0 >= 0) & (y0 < H_);
        bool vy1 = (y1 >= 0) & (y1 < H_);
        bool vx0 = (x0 >= 0) & (x0 < W_);
        bool vx1 = (x1 >= 0) & (x1 < W_);

        int cy0 = min(max(y0, 0), H_ - 1);
        int cy1 = min(max(y1, 0), H_ - 1);
        int cx0 = min(max(x0, 0), W_ - 1);
        int cx1 = min(max(x1, 0), W_ - 1);

        s_idx[k][0][pxl] = cy0 * W_ + cx0;  s_cw[k][0][pxl] = (vy0 & vx0) ? hy * hx : 0.f;
        s_idx[k][1][pxl] = cy0 * W_ + cx1;  s_cw[k][1][pxl] = (vy0 & vx1) ? hy * lx : 0.f;
        s_idx[k][2][pxl] = cy1 * W_ + cx0;  s_cw[k][2][pxl] = (vy1 & vx0) ? ly * hx : 0.f;
        s_idx[k][3][pxl] = cy1 * W_ + cx1;  s_cw[k][3][pxl] = (vy1 & vx1) ? ly * lx : 0.f;
    }
    __syncthreads();

    // ---- Phase B: accumulate one group's 8 output channels ----
    const int tx  = threadIdx.x & 31;   // pixel lane
    const int g   = threadIdx.x >> 5;   // group
    const int pix = pix0 + tx;
    const int b   = pix / HW_;
    const int hw  = pix % HW_;

    float acc[CG_];
#pragma unroll
    for (int co = 0; co < CG_; co++) acc[co] = sb[g * CG_ + co];

    const float* wg = sw + g * CG_ * KK_ * CG_;          // [ci][k][co]
    const float* xb = x + ((size_t)b * C_ + g * CG_) * HW_;

#pragma unroll
    for (int k = 0; k < KK_; k++) {
        const int   i0 = s_idx[k][0][tx];
        const int   i1 = s_idx[k][1][tx];
        const int   i2 = s_idx[k][2][tx];
        const int   i3 = s_idx[k][3][tx];
        const float w0 = s_cw[k][0][tx];
        const float w1 = s_cw[k][1][tx];
        const float w2 = s_cw[k][2][tx];
        const float w3 = s_cw[k][3][tx];

#pragma unroll
        for (int ci = 0; ci < CG_; ci++) {
            const float* base = xb + ci * HW_;
            float v = w0 * __ldg(base + i0)
                    + w1 * __ldg(base + i1)
                    + w2 * __ldg(base + i2)
                    + w3 * __ldg(base + i3);
            const float4* wv = (const float4*)(wg + (ci * KK_ + k) * CG_);
            float4 a0 = wv[0];
            float4 a1 = wv[1];
            acc[0] += v * a0.x;  acc[1] += v * a0.y;
            acc[2] += v * a0.z;  acc[3] += v * a0.w;
            acc[4] += v * a1.x;  acc[5] += v * a1.y;
            acc[6] += v * a1.z;  acc[7] += v * a1.w;
        }
    }

    float* ob = out + ((size_t)b * C_ + g * CG_) * HW_ + hw;
#pragma unroll
    for (int co = 0; co < CG_; co++)
        ob[co * HW_] = acc[co];
}

// ---------------------------------------------------------------------------
// Launch
// ---------------------------------------------------------------------------
extern "C" void kernel_launch(void* const* d_in, const int* in_sizes, int n_in,
                              void* d_out, int out_size)
{
    const float* x    = (const float*)d_in[0];  // [8,64,128,128]
    const float* ow   = (const float*)d_in[1];  // [18,64,3,3]
    const float* ob   = (const float*)d_in[2];  // [18]
    const float* pa   = (const float*)d_in[3];  // [1]
    const float* dwgt = (const float*)d_in[4];  // [64,8,3,3]
    const float* dbia = (const float*)d_in[5];  // [64]
    float* out = (float*)d_out;

    dim3 g1(W_ / TILE, H_ / TILE, B_);          // (8, 8, 8)
    offset_conv_kernel<<<g1, 256>>>(x, ow, ob, pa);

    const int blocks = (B_ * HW_) / 32;         // 4096
    dconv_kernel<<<blocks, 256>>>(x, dwgt, dbia, out);
}